// round 16
// baseline (speedup 1.0000x reference)
#include <cuda_runtime.h>
#include <cuda_fp16.h>
#include <mma.h>

using namespace nvcuda::wmma;

// ---------------------------------------------------------------------------
// LSTMActorCritic: NSEQ=256, T=1024, OBS=128, ACT=16, H=64, N=262144
//
//  K0 prep_kernel   : one-time fp32->fp16 weight conversion (MLP weights).
//  K1 mlp_gx_kernel : tensor-core fused GEMM chain. NEW: MULTI-TILE blocks —
//                     grid (512,2), each block stages weights ONCE and then
//                     processes 4 row-tiles (amortizes staging + barrier ramp;
//                     waves 27.7 -> 6.9). fp16 gx store (R14).
//  K2 lstm_kernel   : R6-EXACT structure; gx fp16 (R14).
//  K3 heads_kernel  : R6-EXACT.
// ---------------------------------------------------------------------------

typedef unsigned long long ull;

#define NSEQ   256
#define TLEN   1024
#define NROWS  262144      // NSEQ*TLEN
#define OBSD   128
#define HID    64
#define GATES  256         // 4*HID
#define ACT    16
#define PF     8           // gx prefetch depth (steps)
#define MTILES 4           // row-tiles per MLP block

// Scratch
__device__ __half d_gxh[2ull * NROWS * GATES];  // 268 MB, gx = feat@Wih.T (no bias), fp16
__device__ float  d_lat[2ull * NROWS * HID];    // 134 MB

// Pre-converted fp16 weights (MLP path only)
__device__ __half g_w1h [2][64 * OBSD];
__device__ __half g_w2h [2][64 * 64];
__device__ __half g_wihh[2][GATES * HID];

// ---------------- packed fp32x2 helpers ----------------
__device__ __forceinline__ ull pk2(float lo, float hi) {
    ull r; asm("mov.b64 %0,{%1,%2};" : "=l"(r) : "f"(lo), "f"(hi)); return r;
}
__device__ __forceinline__ float hsum2(ull v) {
    float a, b; asm("mov.b64 {%0,%1}, %2;" : "=f"(a), "=f"(b) : "l"(v)); return a + b;
}
__device__ __forceinline__ void fma2(ull &acc, ull a, ull b) {
    asm("fma.rn.f32x2 %0,%1,%2,%0;" : "+l"(acc) : "l"(a), "l"(b));
}

__device__ __forceinline__ float sigmoidf_(float x) {
    return __fdividef(1.f, 1.f + __expf(-x));
}
__device__ __forceinline__ float tanhf_(float x) {
    float e = __expf(-2.f * fabsf(x));
    float t = __fdividef(1.f - e, 1.f + e);
    return copysignf(t, x);
}

// ---------------------------------------------------------------------------
// K0: weight prep
// ---------------------------------------------------------------------------
extern "C" __global__ void __launch_bounds__(256)
prep_kernel(const float* __restrict__ Wp1, const float* __restrict__ Wv1,
            const float* __restrict__ Wp2, const float* __restrict__ Wv2,
            const float* __restrict__ Wih_pi, const float* __restrict__ Wih_vf)
{
    const int tid = blockIdx.x * blockDim.x + threadIdx.x;
    const int nth = gridDim.x * blockDim.x;
    for (int i = tid; i < 64 * OBSD; i += nth) {
        g_w1h[0][i] = __float2half(Wp1[i]);
        g_w1h[1][i] = __float2half(Wv1[i]);
    }
    for (int i = tid; i < 64 * 64; i += nth) {
        g_w2h[0][i] = __float2half(Wp2[i]);
        g_w2h[1][i] = __float2half(Wv2[i]);
    }
    for (int i = tid; i < GATES * HID; i += nth) {
        g_wihh[0][i] = __float2half(Wih_pi[i]);
        g_wihh[1][i] = __float2half(Wih_vf[i]);
    }
}

// ---------------------------------------------------------------------------
// K1: tensor-core MLP + gate precompute, multi-tile.
// grid (512, 2), block 256 (8 warps). Weights staged once; MTILES row-tiles
// processed per block.
// ---------------------------------------------------------------------------
extern "C" __global__ void __launch_bounds__(256)
mlp_gx_kernel(const float* __restrict__ obs,
              const float* __restrict__ bp1, const float* __restrict__ bp2,
              const float* __restrict__ bv1, const float* __restrict__ bv2)
{
    extern __shared__ char smem[];
    __half* s_x   = (__half*)(smem);             // ld 136 (region 36864B)
    float*  s_f   = (float*)(smem);              // ld 72  (alias)
    __half* s_w1  = (__half*)(smem + 36864);     // 16384B
    __half* s_w2  = (__half*)(smem + 53248);     // 8192B
    __half* s_wih = (__half*)(smem + 61440);     // 32768B
    __half* s_a   = (__half*)(smem + 94208);     // 18432B
    float*  s_b1  = (float*)(smem + 112640);
    float*  s_b2  = s_b1 + 64;

    const int tid    = threadIdx.x;
    const int warp   = tid >> 5;
    const int branch = blockIdx.y;

    const float* b1 = branch ? bv1 : bp1;
    const float* b2 = branch ? bv2 : bp2;
    __half* gx = d_gxh + (size_t)branch * NROWS * GATES;

    // stage fp16 weights ONCE per block (vectorized copies)
    {
        const uint4* w1g  = (const uint4*)g_w1h[branch];
        const uint4* w2g  = (const uint4*)g_w2h[branch];
        const uint4* wihg = (const uint4*)g_wihh[branch];
        uint4* w1s  = (uint4*)s_w1;
        uint4* w2s  = (uint4*)s_w2;
        uint4* wihs = (uint4*)s_wih;
        #pragma unroll
        for (int i = 0; i < 4; i++)  w1s[tid + 256 * i]  = w1g[tid + 256 * i];
        #pragma unroll
        for (int i = 0; i < 2; i++)  if (tid + 256 * i < 512) w2s[tid + 256 * i] = w2g[tid + 256 * i];
        #pragma unroll
        for (int i = 0; i < 8; i++)  wihs[tid + 256 * i] = wihg[tid + 256 * i];
    }
    if (tid < 64)       s_b1[tid]      = b1[tid];
    else if (tid < 128) s_b2[tid - 64] = b2[tid - 64];

    fragment<matrix_a, 16, 16, 16, __half, row_major> fa;
    fragment<matrix_b, 16, 16, 16, __half, col_major> fb;
    fragment<accumulator, 16, 16, 16, float> fc[4];
    fragment<accumulator, 16, 16, 16, __half> fch;

    #pragma unroll 1
    for (int tile = 0; tile < MTILES; tile++) {
        const size_t row0 = ((size_t)blockIdx.x * MTILES + tile) * 128;

        // stage obs tile fp16 — vectorized: 16x (LDG.128 + 2 CVT-pack + STS.64)
        // (safe: s_x aliases s_f, whose last read was before the previous
        //  iteration's epilogue-2 barrier; weights untouched)
        {
            const float4* op = (const float4*)(obs + row0 * OBSD);
            #pragma unroll
            for (int it = 0; it < 16; it++) {
                int i  = tid + it * 256;
                int r  = i >> 5;
                int k4 = i & 31;
                float4 v = op[r * 32 + k4];
                union { __half2 h[2]; uint2 u; } pk;
                pk.h[0] = __floats2half2_rn(v.x, v.y);
                pk.h[1] = __floats2half2_rn(v.z, v.w);
                *(uint2*)(s_x + r * 136 + k4 * 4) = pk.u;
            }
        }
        __syncthreads();   // staging (weights on tile 0) + obs visible

        // ---- Layer 1: [128x128] @ [128x64] ----
        #pragma unroll
        for (int n = 0; n < 4; n++) fill_fragment(fc[n], 0.0f);
        #pragma unroll
        for (int k = 0; k < 8; k++) {
            load_matrix_sync(fa, s_x + warp * 16 * 136 + k * 16, 136);
            #pragma unroll
            for (int n = 0; n < 4; n++) {
                load_matrix_sync(fb, s_w1 + n * 16 * 128 + k * 16, 128);
                mma_sync(fc[n], fa, fb, fc[n]);
            }
        }
        __syncthreads();                       // all warps done reading s_x
        #pragma unroll
        for (int n = 0; n < 4; n++)
            store_matrix_sync(s_f + warp * 16 * 72 + n * 16, fc[n], 72, mem_row_major);
        __syncthreads();
        // epilogue 1 — vectorized
        #pragma unroll
        for (int it = 0; it < 16; it++) {
            int i = tid + it * 256;
            int r = i >> 5, c = (i & 31) * 2;
            float2 f = *(const float2*)(s_f + r * 72 + c);
            *(__half2*)(s_a + r * 72 + c) =
                __floats2half2_rn(tanhf_(f.x + s_b1[c]), tanhf_(f.y + s_b1[c + 1]));
        }
        __syncthreads();

        // ---- Layer 2: [128x64] @ [64x64] ----
        #pragma unroll
        for (int n = 0; n < 4; n++) fill_fragment(fc[n], 0.0f);
        #pragma unroll
        for (int k = 0; k < 4; k++) {
            load_matrix_sync(fa, s_a + warp * 16 * 72 + k * 16, 72);
            #pragma unroll
            for (int n = 0; n < 4; n++) {
                load_matrix_sync(fb, s_w2 + n * 16 * 64 + k * 16, 64);
                mma_sync(fc[n], fa, fb, fc[n]);
            }
        }
        #pragma unroll
        for (int n = 0; n < 4; n++)
            store_matrix_sync(s_f + warp * 16 * 72 + n * 16, fc[n], 72, mem_row_major);
        __syncthreads();
        // epilogue 2 — vectorized
        #pragma unroll
        for (int it = 0; it < 16; it++) {
            int i = tid + it * 256;
            int r = i >> 5, c = (i & 31) * 2;
            float2 f = *(const float2*)(s_f + r * 72 + c);
            *(__half2*)(s_a + r * 72 + c) =
                __floats2half2_rn(tanhf_(f.x + s_b2[c]), tanhf_(f.y + s_b2[c + 1]));
        }
        __syncthreads();

        // ---- Gates: [128x64] @ [64x256], fp32 accum -> fp16 store to gmem ----
        __half* gxw = gx + (row0 + warp * 16) * GATES;
        #pragma unroll 1
        for (int ch = 0; ch < 4; ch++) {
            #pragma unroll
            for (int n = 0; n < 4; n++) fill_fragment(fc[n], 0.0f);
            #pragma unroll
            for (int k = 0; k < 4; k++) {
                load_matrix_sync(fa, s_a + warp * 16 * 72 + k * 16, 72);
                #pragma unroll
                for (int n = 0; n < 4; n++) {
                    load_matrix_sync(fb, s_wih + (ch * 64 + n * 16) * 64 + k * 16, 64);
                    mma_sync(fc[n], fa, fb, fc[n]);
                }
            }
            #pragma unroll
            for (int n = 0; n < 4; n++) {
                #pragma unroll
                for (int e = 0; e < fc[n].num_elements; e++)
                    fch.x[e] = __float2half(fc[n].x[e]);
                store_matrix_sync(gxw + ch * 64 + n * 16, fch, GATES, mem_row_major);
            }
        }
        // next iteration's obs staging is separated from this tile's s_a reads
        // by the obs-staging barrier; s_x/s_f hazards covered as noted above.
    }
}

// ---------------------------------------------------------------------------
// K2: recurrent loop (R6-EXACT structure; gx fp16).
// 256 blocks x 256 threads, 2 seqs/block.
// ---------------------------------------------------------------------------
extern "C" __global__ void __launch_bounds__(256, 2)
lstm_kernel(const float* __restrict__ Whh_pi, const float* __restrict__ Whh_vf,
            const float* __restrict__ eps,
            const float* __restrict__ h0_pi, const float* __restrict__ c0_pi,
            const float* __restrict__ h0_vf, const float* __restrict__ c0_vf,
            const float* __restrict__ bih_pi, const float* __restrict__ bhh_pi,
            const float* __restrict__ bih_vf, const float* __restrict__ bhh_vf)
{
    const int tid  = threadIdx.x;
    const int lstm = blockIdx.x >> 7;
    const int sp   = blockIdx.x & 127;
    const int seqA = sp * 2;

    const float* Whh = lstm ? Whh_vf : Whh_pi;
    const float* h0  = lstm ? h0_vf  : h0_pi;
    const float* c0  = lstm ? c0_vf  : c0_pi;
    const float* bih = lstm ? bih_vf : bih_pi;
    const float* bhh = lstm ? bhh_vf : bhh_pi;
    const __half* gx = d_gxh + (size_t)lstm * NROWS * GATES;
    float*       lat = d_lat + (size_t)lstm * NROWS * HID;

    __shared__ __align__(16) float hs[2][HID];
    __shared__ float gs[2][GATES];
    __shared__ float seps[2][TLEN];

    // stage episode-start rows for both sequences (coalesced)
    {
        const float4* eA = (const float4*)(eps + (size_t)seqA * TLEN);
        float4* sA = (float4*)seps[0];
        sA[tid]       = eA[tid];
        sA[tid + 256] = eA[tid + 256];
    }

    // Whh row tid -> 32 packed pairs in registers; bias folded per-gate
    ull wv[32];
    {
        const float4* wp = (const float4*)(Whh + tid * HID);
        #pragma unroll
        for (int i = 0; i < 16; i++) {
            float4 v = wp[i];
            wv[2*i]   = pk2(v.x, v.y);
            wv[2*i+1] = pk2(v.z, v.w);
        }
    }
    const float bg = bih[tid] + bhh[tid];

    // gx prefetch ring: slots 0..PF-1 hold steps t..t+PF-1 (fp16 -> fp32)
    float gAb[PF], gBb[PF];
    const __half* gxA = gx + (size_t)seqA * TLEN * GATES + tid;
    const __half* gxB = gxA + (size_t)TLEN * GATES;
    #pragma unroll
    for (int p = 0; p < PF; p++) {
        gAb[p] = __half2float(gxA[(size_t)p * GATES]);
        gBb[p] = __half2float(gxB[(size_t)p * GATES]);
    }

    const int s = tid >> 6, j = tid & 63;      // valid for tid < 128
    const int myseq = seqA + s;
    float c = 0.f;
    __syncthreads();                           // seps staged
    if (tid < 128) {
        float m = 1.f - seps[s][0];
        hs[s][j] = h0[myseq * HID + j] * m;
        c        = c0[myseq * HID + j] * m;
    }
    __syncthreads();

    const ulonglong2* hA2 = (const ulonglong2*)hs[0];
    const ulonglong2* hB2 = (const ulonglong2*)hs[1];

    for (int tb = 0; tb < TLEN; tb += PF) {
        #pragma unroll
        for (int u = 0; u < PF; u++) {
            const int t = tb + u;

            ull a0 = 0, a1 = 0, b0 = 0, b1_ = 0;
            #pragma unroll
            for (int kk = 0; kk < 16; kk++) {
                ulonglong2 ha = hA2[kk]; ulonglong2 hb = hB2[kk];
                fma2(a0,  wv[2*kk],   ha.x);  fma2(a1,  wv[2*kk+1], ha.y);
                fma2(b0,  wv[2*kk],   hb.x);  fma2(b1_, wv[2*kk+1], hb.y);
            }
            float gateA = gAb[u] + bg + hsum2(a0) + hsum2(a1);
            float gateB = gBb[u] + bg + hsum2(b0) + hsum2(b1_);

            // refill ring slot u with step t+PF (8 steps ahead)
            if (t + PF < TLEN) {
                gAb[u] = __half2float(gxA[(size_t)(t + PF) * GATES]);
                gBb[u] = __half2float(gxB[(size_t)(t + PF) * GATES]);
            }

            gs[0][tid] = gateA;
            gs[1][tid] = gateB;
            __syncthreads();

            if (tid < 128) {
                float gi = gs[s][j],       gf = gs[s][64 + j];
                float gg = gs[s][128 + j], go = gs[s][192 + j];
                c = sigmoidf_(gf) * c + sigmoidf_(gi) * tanhf_(gg);
                float h = sigmoidf_(go) * tanhf_(c);
                lat[((size_t)myseq * TLEN + t) * HID + j] = h;
                // mask for step t+1 (garbage at t=1023 is never read)
                float m = 1.f - seps[s][(t + 1) & (TLEN - 1)];
                c *= m;
                hs[s][j] = h * m;
            }
            __syncthreads();
        }
    }
}

// ---------------------------------------------------------------------------
// K3: heads (R6-EXACT). grid 2048 blocks, 128 threads, 128 rows/block.
// ---------------------------------------------------------------------------
extern "C" __global__ void __launch_bounds__(128)
heads_kernel(const int* __restrict__ action,
             const float* __restrict__ Wa, const float* __restrict__ ba,
             const float* __restrict__ Wc, const float* __restrict__ bc,
             float* __restrict__ out)
{
    __shared__ float tile[64 * 129];
    __shared__ float was[ACT * HID];
    __shared__ float bas[ACT];
    __shared__ float wcs[HID];
    __shared__ float bcs;

    const int tid = threadIdx.x;
    const int r0  = blockIdx.x * 128;
    const float* lat_pi = d_lat;
    const float* lat_vf = d_lat + (size_t)NROWS * HID;

    for (int i = tid; i < ACT * HID; i += 128) was[i] = Wa[i];
    if (tid < ACT) bas[tid] = ba[tid];
    if (tid < HID) wcs[tid] = Wc[tid];
    if (tid == 0)  bcs = bc[0];

    for (int i = tid; i < 128 * HID; i += 128) {
        int r = i >> 6, k = i & 63;
        tile[k * 129 + r] = lat_pi[(size_t)r0 * HID + i];
    }
    __syncthreads();

    const int n = r0 + tid;
    float l[ACT];
    #pragma unroll
    for (int a = 0; a < ACT; a++) l[a] = bas[a];
    #pragma unroll 1
    for (int k = 0; k < HID; k++) {
        float x = tile[k * 129 + tid];
        #pragma unroll
        for (int a = 0; a < ACT; a++) l[a] = fmaf(was[a * HID + k], x, l[a]);
    }

    float m = l[0];
    #pragma unroll
    for (int a = 1; a < ACT; a++) m = fmaxf(m, l[a]);
    float se = 0.f;
    #pragma unroll
    for (int a = 0; a < ACT; a++) se += __expf(l[a] - m);
    float lse = m + __logf(se);
    float ent = 0.f;
    #pragma unroll
    for (int a = 0; a < ACT; a++) { float lp = l[a] - lse; ent += __expf(lp) * lp; }
    int   act   = action[n];
    float lpact = l[act] - lse;
    __syncthreads();

    for (int i = tid; i < 128 * HID; i += 128) {
        int r = i >> 6, k = i & 63;
        tile[k * 129 + r] = lat_vf[(size_t)r0 * HID + i];
    }
    __syncthreads();

    float v = bcs;
    #pragma unroll
    for (int k = 0; k < HID; k++) v = fmaf(wcs[k], tile[k * 129 + tid], v);

    out[n]             = lpact;
    out[NROWS + n]     = -ent;
    out[2 * NROWS + n] = v;
}

// ---------------------------------------------------------------------------
extern "C" void kernel_launch(void* const* d_in, const int* in_sizes, int n_in,
                              void* d_out, int out_size)
{
    const float* obs     = (const float*)d_in[0];
    const int*   action  = (const int*)  d_in[1];
    const float* eps     = (const float*)d_in[2];
    const float* h_pi    = (const float*)d_in[3];
    const float* c_pi    = (const float*)d_in[4];
    const float* h_vf    = (const float*)d_in[5];
    const float* c_vf    = (const float*)d_in[6];
    const float* Wp1     = (const float*)d_in[7];
    const float* bp1     = (const float*)d_in[8];
    const float* Wp2     = (const float*)d_in[9];
    const float* bp2     = (const float*)d_in[10];
    const float* Wv1     = (const float*)d_in[11];
    const float* bv1     = (const float*)d_in[12];
    const float* Wv2     = (const float*)d_in[13];
    const float* bv2     = (const float*)d_in[14];
    const float* Wih_pi  = (const float*)d_in[15];
    const float* Whh_pi  = (const float*)d_in[16];
    const float* bih_pi  = (const float*)d_in[17];
    const float* bhh_pi  = (const float*)d_in[18];
    const float* Wih_vf  = (const float*)d_in[19];
    const float* Whh_vf  = (const float*)d_in[20];
    const float* bih_vf  = (const float*)d_in[21];
    const float* bhh_vf  = (const float*)d_in[22];
    const float* Wa      = (const float*)d_in[23];
    const float* ba      = (const float*)d_in[24];
    const float* Wc      = (const float*)d_in[25];
    const float* bc      = (const float*)d_in[26];
    float* out = (float*)d_out;

    const int SMEM_MLP = 114688;
    cudaFuncSetAttribute(mlp_gx_kernel, cudaFuncAttributeMaxDynamicSharedMemorySize, SMEM_MLP);

    prep_kernel<<<64, 256>>>(Wp1, Wv1, Wp2, Wv2, Wih_pi, Wih_vf);

    mlp_gx_kernel<<<dim3(512, 2), 256, SMEM_MLP>>>(obs, bp1, bp2, bv1, bv2);

    lstm_kernel<<<256, 256>>>(Whh_pi, Whh_vf, eps, h_pi, c_pi, h_vf, c_vf,
                              bih_pi, bhh_pi, bih_vf, bhh_vf);

    heads_kernel<<<2048, 128>>>(action, Wa, ba, Wc, bc, out);
}

// round 17
// speedup vs baseline: 1.0657x; 1.0657x over previous
#include <cuda_runtime.h>
#include <cuda_fp16.h>
#include <mma.h>

using namespace nvcuda::wmma;

// ---------------------------------------------------------------------------
// LSTMActorCritic: NSEQ=256, T=1024, OBS=128, ACT=16, H=64, N=262144
//
//  K0 prep_kernel   : one-time fp32->fp16 weight conversion (MLP weights).
//  K1 mlp_gx_kernel : R14-EXACT (single-tile blocks, grid (2048,2); multi-tile
//                     R16 regressed — many small blocks overlap better).
//  K2 lstm_kernel   : R6-EXACT structure; gx fp16 (R14).
//  K3 heads_kernel  : NEW — no smem tile/barriers, per-thread row streaming,
//                     f32x2 packed math (512 fma2 vs 1024 FFMA).
// ---------------------------------------------------------------------------

typedef unsigned long long ull;

#define NSEQ   256
#define TLEN   1024
#define NROWS  262144      // NSEQ*TLEN
#define OBSD   128
#define HID    64
#define GATES  256         // 4*HID
#define ACT    16
#define PF     8           // gx prefetch depth (steps)

// Scratch
__device__ __half d_gxh[2ull * NROWS * GATES];  // 268 MB, gx = feat@Wih.T (no bias), fp16
__device__ float  d_lat[2ull * NROWS * HID];    // 134 MB

// Pre-converted fp16 weights (MLP path only)
__device__ __half g_w1h [2][64 * OBSD];
__device__ __half g_w2h [2][64 * 64];
__device__ __half g_wihh[2][GATES * HID];

// ---------------- packed fp32x2 helpers ----------------
__device__ __forceinline__ ull pk2(float lo, float hi) {
    ull r; asm("mov.b64 %0,{%1,%2};" : "=l"(r) : "f"(lo), "f"(hi)); return r;
}
__device__ __forceinline__ float hsum2(ull v) {
    float a, b; asm("mov.b64 {%0,%1}, %2;" : "=f"(a), "=f"(b) : "l"(v)); return a + b;
}
__device__ __forceinline__ void fma2(ull &acc, ull a, ull b) {
    asm("fma.rn.f32x2 %0,%1,%2,%0;" : "+l"(acc) : "l"(a), "l"(b));
}

__device__ __forceinline__ float sigmoidf_(float x) {
    return __fdividef(1.f, 1.f + __expf(-x));
}
__device__ __forceinline__ float tanhf_(float x) {
    float e = __expf(-2.f * fabsf(x));
    float t = __fdividef(1.f - e, 1.f + e);
    return copysignf(t, x);
}

// ---------------------------------------------------------------------------
// K0: weight prep
// ---------------------------------------------------------------------------
extern "C" __global__ void __launch_bounds__(256)
prep_kernel(const float* __restrict__ Wp1, const float* __restrict__ Wv1,
            const float* __restrict__ Wp2, const float* __restrict__ Wv2,
            const float* __restrict__ Wih_pi, const float* __restrict__ Wih_vf)
{
    const int tid = blockIdx.x * blockDim.x + threadIdx.x;
    const int nth = gridDim.x * blockDim.x;
    for (int i = tid; i < 64 * OBSD; i += nth) {
        g_w1h[0][i] = __float2half(Wp1[i]);
        g_w1h[1][i] = __float2half(Wv1[i]);
    }
    for (int i = tid; i < 64 * 64; i += nth) {
        g_w2h[0][i] = __float2half(Wp2[i]);
        g_w2h[1][i] = __float2half(Wv2[i]);
    }
    for (int i = tid; i < GATES * HID; i += nth) {
        g_wihh[0][i] = __float2half(Wih_pi[i]);
        g_wihh[1][i] = __float2half(Wih_vf[i]);
    }
}

// ---------------------------------------------------------------------------
// K1: tensor-core MLP + gate precompute (R14-EXACT). grid (2048,2), block 256.
// ---------------------------------------------------------------------------
extern "C" __global__ void __launch_bounds__(256)
mlp_gx_kernel(const float* __restrict__ obs,
              const float* __restrict__ bp1, const float* __restrict__ bp2,
              const float* __restrict__ bv1, const float* __restrict__ bv2)
{
    extern __shared__ char smem[];
    __half* s_x   = (__half*)(smem);             // ld 136 (region 36864B)
    float*  s_f   = (float*)(smem);              // ld 72  (alias)
    __half* s_w1  = (__half*)(smem + 36864);     // 16384B
    __half* s_w2  = (__half*)(smem + 53248);     // 8192B
    __half* s_wih = (__half*)(smem + 61440);     // 32768B
    __half* s_a   = (__half*)(smem + 94208);     // 18432B
    float*  s_b1  = (float*)(smem + 112640);
    float*  s_b2  = s_b1 + 64;

    const int tid    = threadIdx.x;
    const int warp   = tid >> 5;
    const int branch = blockIdx.y;

    const float* b1 = branch ? bv1 : bp1;
    const float* b2 = branch ? bv2 : bp2;
    __half* gx = d_gxh + (size_t)branch * NROWS * GATES;

    // stage fp16 weights (vectorized copies)
    {
        const uint4* w1g  = (const uint4*)g_w1h[branch];
        const uint4* w2g  = (const uint4*)g_w2h[branch];
        const uint4* wihg = (const uint4*)g_wihh[branch];
        uint4* w1s  = (uint4*)s_w1;
        uint4* w2s  = (uint4*)s_w2;
        uint4* wihs = (uint4*)s_wih;
        #pragma unroll
        for (int i = 0; i < 4; i++)  w1s[tid + 256 * i]  = w1g[tid + 256 * i];
        #pragma unroll
        for (int i = 0; i < 2; i++)  if (tid + 256 * i < 512) w2s[tid + 256 * i] = w2g[tid + 256 * i];
        #pragma unroll
        for (int i = 0; i < 8; i++)  wihs[tid + 256 * i] = wihg[tid + 256 * i];
    }
    if (tid < 64)       s_b1[tid]      = b1[tid];
    else if (tid < 128) s_b2[tid - 64] = b2[tid - 64];

    // stage obs tile fp16 — vectorized: 16x (LDG.128 + 2 CVT-pack + STS.64)
    const size_t row0 = (size_t)blockIdx.x * 128;
    {
        const float4* op = (const float4*)(obs + row0 * OBSD);
        #pragma unroll
        for (int it = 0; it < 16; it++) {
            int i  = tid + it * 256;
            int r  = i >> 5;
            int k4 = i & 31;
            float4 v = op[r * 32 + k4];
            union { __half2 h[2]; uint2 u; } pk;
            pk.h[0] = __floats2half2_rn(v.x, v.y);
            pk.h[1] = __floats2half2_rn(v.z, v.w);
            *(uint2*)(s_x + r * 136 + k4 * 4) = pk.u;
        }
    }
    __syncthreads();

    fragment<matrix_a, 16, 16, 16, __half, row_major> fa;
    fragment<matrix_b, 16, 16, 16, __half, col_major> fb;
    fragment<accumulator, 16, 16, 16, float> fc[4];
    fragment<accumulator, 16, 16, 16, __half> fch;

    // ---- Layer 1: [128x128] @ [128x64] ----
    #pragma unroll
    for (int n = 0; n < 4; n++) fill_fragment(fc[n], 0.0f);
    #pragma unroll
    for (int k = 0; k < 8; k++) {
        load_matrix_sync(fa, s_x + warp * 16 * 136 + k * 16, 136);
        #pragma unroll
        for (int n = 0; n < 4; n++) {
            load_matrix_sync(fb, s_w1 + n * 16 * 128 + k * 16, 128);
            mma_sync(fc[n], fa, fb, fc[n]);
        }
    }
    __syncthreads();                       // all warps done reading s_x
    #pragma unroll
    for (int n = 0; n < 4; n++)
        store_matrix_sync(s_f + warp * 16 * 72 + n * 16, fc[n], 72, mem_row_major);
    __syncthreads();
    // epilogue 1 — vectorized
    #pragma unroll
    for (int it = 0; it < 16; it++) {
        int i = tid + it * 256;
        int r = i >> 5, c = (i & 31) * 2;
        float2 f = *(const float2*)(s_f + r * 72 + c);
        *(__half2*)(s_a + r * 72 + c) =
            __floats2half2_rn(tanhf_(f.x + s_b1[c]), tanhf_(f.y + s_b1[c + 1]));
    }
    __syncthreads();

    // ---- Layer 2: [128x64] @ [64x64] ----
    #pragma unroll
    for (int n = 0; n < 4; n++) fill_fragment(fc[n], 0.0f);
    #pragma unroll
    for (int k = 0; k < 4; k++) {
        load_matrix_sync(fa, s_a + warp * 16 * 72 + k * 16, 72);
        #pragma unroll
        for (int n = 0; n < 4; n++) {
            load_matrix_sync(fb, s_w2 + n * 16 * 64 + k * 16, 64);
            mma_sync(fc[n], fa, fb, fc[n]);
        }
    }
    #pragma unroll
    for (int n = 0; n < 4; n++)
        store_matrix_sync(s_f + warp * 16 * 72 + n * 16, fc[n], 72, mem_row_major);
    __syncthreads();
    // epilogue 2 — vectorized
    #pragma unroll
    for (int it = 0; it < 16; it++) {
        int i = tid + it * 256;
        int r = i >> 5, c = (i & 31) * 2;
        float2 f = *(const float2*)(s_f + r * 72 + c);
        *(__half2*)(s_a + r * 72 + c) =
            __floats2half2_rn(tanhf_(f.x + s_b2[c]), tanhf_(f.y + s_b2[c + 1]));
    }
    __syncthreads();

    // ---- Gates: [128x64] @ [64x256], fp32 accum -> fp16 store to gmem ----
    __half* gxw = gx + (row0 + warp * 16) * GATES;
    #pragma unroll 1
    for (int ch = 0; ch < 4; ch++) {
        #pragma unroll
        for (int n = 0; n < 4; n++) fill_fragment(fc[n], 0.0f);
        #pragma unroll
        for (int k = 0; k < 4; k++) {
            load_matrix_sync(fa, s_a + warp * 16 * 72 + k * 16, 72);
            #pragma unroll
            for (int n = 0; n < 4; n++) {
                load_matrix_sync(fb, s_wih + (ch * 64 + n * 16) * 64 + k * 16, 64);
                mma_sync(fc[n], fa, fb, fc[n]);
            }
        }
        #pragma unroll
        for (int n = 0; n < 4; n++) {
            #pragma unroll
            for (int e = 0; e < fc[n].num_elements; e++)
                fch.x[e] = __float2half(fc[n].x[e]);
            store_matrix_sync(gxw + ch * 64 + n * 16, fch, GATES, mem_row_major);
        }
    }
}

// ---------------------------------------------------------------------------
// K2: recurrent loop (R6-EXACT structure; gx fp16).
// 256 blocks x 256 threads, 2 seqs/block.
// ---------------------------------------------------------------------------
extern "C" __global__ void __launch_bounds__(256, 2)
lstm_kernel(const float* __restrict__ Whh_pi, const float* __restrict__ Whh_vf,
            const float* __restrict__ eps,
            const float* __restrict__ h0_pi, const float* __restrict__ c0_pi,
            const float* __restrict__ h0_vf, const float* __restrict__ c0_vf,
            const float* __restrict__ bih_pi, const float* __restrict__ bhh_pi,
            const float* __restrict__ bih_vf, const float* __restrict__ bhh_vf)
{
    const int tid  = threadIdx.x;
    const int lstm = blockIdx.x >> 7;
    const int sp   = blockIdx.x & 127;
    const int seqA = sp * 2;

    const float* Whh = lstm ? Whh_vf : Whh_pi;
    const float* h0  = lstm ? h0_vf  : h0_pi;
    const float* c0  = lstm ? c0_vf  : c0_pi;
    const float* bih = lstm ? bih_vf : bih_pi;
    const float* bhh = lstm ? bhh_vf : bhh_pi;
    const __half* gx = d_gxh + (size_t)lstm * NROWS * GATES;
    float*       lat = d_lat + (size_t)lstm * NROWS * HID;

    __shared__ __align__(16) float hs[2][HID];
    __shared__ float gs[2][GATES];
    __shared__ float seps[2][TLEN];

    // stage episode-start rows for both sequences (coalesced)
    {
        const float4* eA = (const float4*)(eps + (size_t)seqA * TLEN);
        float4* sA = (float4*)seps[0];
        sA[tid]       = eA[tid];
        sA[tid + 256] = eA[tid + 256];
    }

    // Whh row tid -> 32 packed pairs in registers; bias folded per-gate
    ull wv[32];
    {
        const float4* wp = (const float4*)(Whh + tid * HID);
        #pragma unroll
        for (int i = 0; i < 16; i++) {
            float4 v = wp[i];
            wv[2*i]   = pk2(v.x, v.y);
            wv[2*i+1] = pk2(v.z, v.w);
        }
    }
    const float bg = bih[tid] + bhh[tid];

    // gx prefetch ring: slots 0..PF-1 hold steps t..t+PF-1 (fp16 -> fp32)
    float gAb[PF], gBb[PF];
    const __half* gxA = gx + (size_t)seqA * TLEN * GATES + tid;
    const __half* gxB = gxA + (size_t)TLEN * GATES;
    #pragma unroll
    for (int p = 0; p < PF; p++) {
        gAb[p] = __half2float(gxA[(size_t)p * GATES]);
        gBb[p] = __half2float(gxB[(size_t)p * GATES]);
    }

    const int s = tid >> 6, j = tid & 63;      // valid for tid < 128
    const int myseq = seqA + s;
    float c = 0.f;
    __syncthreads();                           // seps staged
    if (tid < 128) {
        float m = 1.f - seps[s][0];
        hs[s][j] = h0[myseq * HID + j] * m;
        c        = c0[myseq * HID + j] * m;
    }
    __syncthreads();

    const ulonglong2* hA2 = (const ulonglong2*)hs[0];
    const ulonglong2* hB2 = (const ulonglong2*)hs[1];

    for (int tb = 0; tb < TLEN; tb += PF) {
        #pragma unroll
        for (int u = 0; u < PF; u++) {
            const int t = tb + u;

            ull a0 = 0, a1 = 0, b0 = 0, b1_ = 0;
            #pragma unroll
            for (int kk = 0; kk < 16; kk++) {
                ulonglong2 ha = hA2[kk]; ulonglong2 hb = hB2[kk];
                fma2(a0,  wv[2*kk],   ha.x);  fma2(a1,  wv[2*kk+1], ha.y);
                fma2(b0,  wv[2*kk],   hb.x);  fma2(b1_, wv[2*kk+1], hb.y);
            }
            float gateA = gAb[u] + bg + hsum2(a0) + hsum2(a1);
            float gateB = gBb[u] + bg + hsum2(b0) + hsum2(b1_);

            // refill ring slot u with step t+PF (8 steps ahead)
            if (t + PF < TLEN) {
                gAb[u] = __half2float(gxA[(size_t)(t + PF) * GATES]);
                gBb[u] = __half2float(gxB[(size_t)(t + PF) * GATES]);
            }

            gs[0][tid] = gateA;
            gs[1][tid] = gateB;
            __syncthreads();

            if (tid < 128) {
                float gi = gs[s][j],       gf = gs[s][64 + j];
                float gg = gs[s][128 + j], go = gs[s][192 + j];
                c = sigmoidf_(gf) * c + sigmoidf_(gi) * tanhf_(gg);
                float h = sigmoidf_(go) * tanhf_(c);
                lat[((size_t)myseq * TLEN + t) * HID + j] = h;
                // mask for step t+1 (garbage at t=1023 is never read)
                float m = 1.f - seps[s][(t + 1) & (TLEN - 1)];
                c *= m;
                hs[s][j] = h * m;
            }
            __syncthreads();
        }
    }
}

// ---------------------------------------------------------------------------
// K3: heads v2 — no smem tile, per-thread row streaming, f32x2 packed math.
// grid 2048 blocks, 128 threads, 1 row/thread.
// ---------------------------------------------------------------------------
extern "C" __global__ void __launch_bounds__(128)
heads_kernel(const int* __restrict__ action,
             const float* __restrict__ Wa, const float* __restrict__ ba,
             const float* __restrict__ Wc, const float* __restrict__ bc,
             float* __restrict__ out)
{
    __shared__ ull   w2s[ACT * 32];   // Wa rows as f32x2 pairs
    __shared__ float bas[ACT];
    __shared__ ull   wc2[32];         // Wc as pairs
    __shared__ float bcs;

    const int tid = threadIdx.x;
    const int n   = blockIdx.x * 128 + tid;
    const float* lat_pi = d_lat;
    const float* lat_vf = d_lat + (size_t)NROWS * HID;

    // stage packed head weights
    for (int i = tid; i < ACT * 32; i += 128) {
        int a = i >> 5, kk = i & 31;
        w2s[i] = pk2(Wa[a * HID + 2 * kk], Wa[a * HID + 2 * kk + 1]);
    }
    if (tid < ACT) bas[tid] = ba[tid];
    if (tid < 32)  wc2[tid] = pk2(Wc[2 * tid], Wc[2 * tid + 1]);
    if (tid == 0)  bcs = bc[0];
    __syncthreads();

    // ---- policy head: stream lat_pi row into packed registers ----
    ull h2[32];
    {
        const float4* hp = (const float4*)(lat_pi + (size_t)n * HID);
        #pragma unroll
        for (int i = 0; i < 16; i++) {
            float4 v = hp[i];
            h2[2*i]   = pk2(v.x, v.y);
            h2[2*i+1] = pk2(v.z, v.w);
        }
    }

    float l[ACT];
    #pragma unroll
    for (int a = 0; a < ACT; a += 2) {
        ull acc0 = 0, acc1 = 0;
        const ull* w0 = w2s + a * 32;
        const ull* w1 = w2s + (a + 1) * 32;
        #pragma unroll
        for (int kk = 0; kk < 32; kk++) {
            fma2(acc0, w0[kk], h2[kk]);
            fma2(acc1, w1[kk], h2[kk]);
        }
        l[a]     = hsum2(acc0) + bas[a];
        l[a + 1] = hsum2(acc1) + bas[a + 1];
    }

    float m = l[0];
    #pragma unroll
    for (int a = 1; a < ACT; a++) m = fmaxf(m, l[a]);
    float se = 0.f;
    #pragma unroll
    for (int a = 0; a < ACT; a++) se += __expf(l[a] - m);
    float lse = m + __logf(se);
    float ent = 0.f;
    #pragma unroll
    for (int a = 0; a < ACT; a++) { float lp = l[a] - lse; ent += __expf(lp) * lp; }
    int   act   = action[n];
    float lpact = l[act] - lse;

    // ---- value head: stream lat_vf row ----
    {
        const float4* hp = (const float4*)(lat_vf + (size_t)n * HID);
        #pragma unroll
        for (int i = 0; i < 16; i++) {
            float4 v = hp[i];
            h2[2*i]   = pk2(v.x, v.y);
            h2[2*i+1] = pk2(v.z, v.w);
        }
    }
    ull accv = 0;
    #pragma unroll
    for (int kk = 0; kk < 32; kk++) fma2(accv, wc2[kk], h2[kk]);
    float v = hsum2(accv) + bcs;

    out[n]             = lpact;
    out[NROWS + n]     = -ent;
    out[2 * NROWS + n] = v;
}

// ---------------------------------------------------------------------------
extern "C" void kernel_launch(void* const* d_in, const int* in_sizes, int n_in,
                              void* d_out, int out_size)
{
    const float* obs     = (const float*)d_in[0];
    const int*   action  = (const int*)  d_in[1];
    const float* eps     = (const float*)d_in[2];
    const float* h_pi    = (const float*)d_in[3];
    const float* c_pi    = (const float*)d_in[4];
    const float* h_vf    = (const float*)d_in[5];
    const float* c_vf    = (const float*)d_in[6];
    const float* Wp1     = (const float*)d_in[7];
    const float* bp1     = (const float*)d_in[8];
    const float* Wp2     = (const float*)d_in[9];
    const float* bp2     = (const float*)d_in[10];
    const float* Wv1     = (const float*)d_in[11];
    const float* bv1     = (const float*)d_in[12];
    const float* Wv2     = (const float*)d_in[13];
    const float* bv2     = (const float*)d_in[14];
    const float* Wih_pi  = (const float*)d_in[15];
    const float* Whh_pi  = (const float*)d_in[16];
    const float* bih_pi  = (const float*)d_in[17];
    const float* bhh_pi  = (const float*)d_in[18];
    const float* Wih_vf  = (const float*)d_in[19];
    const float* Whh_vf  = (const float*)d_in[20];
    const float* bih_vf  = (const float*)d_in[21];
    const float* bhh_vf  = (const float*)d_in[22];
    const float* Wa      = (const float*)d_in[23];
    const float* ba      = (const float*)d_in[24];
    const float* Wc      = (const float*)d_in[25];
    const float* bc      = (const float*)d_in[26];
    float* out = (float*)d_out;

    const int SMEM_MLP = 114688;
    cudaFuncSetAttribute(mlp_gx_kernel, cudaFuncAttributeMaxDynamicSharedMemorySize, SMEM_MLP);

    prep_kernel<<<64, 256>>>(Wp1, Wv1, Wp2, Wv2, Wih_pi, Wih_vf);

    mlp_gx_kernel<<<dim3(2048, 2), 256, SMEM_MLP>>>(obs, bp1, bp2, bv1, bv2);

    lstm_kernel<<<256, 256>>>(Whh_pi, Whh_vf, eps, h_pi, c_pi, h_vf, c_vf,
                              bih_pi, bhh_pi, bih_vf, bhh_vf);

    heads_kernel<<<2048, 128>>>(action, Wa, ba, Wc, bc, out);
}